// round 3
// baseline (speedup 1.0000x reference)
#include <cuda_runtime.h>
#include <math.h>

#define Bsz   32
#define Tlen  128
#define Ulen  64
#define ENCD  512
#define DECD  512
#define ATTND 256
#define EMBD  256
#define VOCAB 32000
#define GIN   768     // EMB + ENC
#define G3    1536    // 3 * DEC
#define HCW   1024    // DEC + ENC

#define NB 132
#define NT 256
#define NTH (NB * NT)
#define NWARPS (NTH / 32)

// ---------------- scratch (static device globals; no allocation) ----------------
__device__ float g_Wh[Bsz * Tlen * ATTND];          // 4 MB
__device__ float g_Ws[Bsz * ATTND];
__device__ float g_e[Bsz * Tlen];
__device__ float g_c[Bsz * ENCD];
__device__ float g_h[Bsz * DECD];
__device__ float g_gh[Bsz * G3];
__device__ float g_hc[Bsz * Ulen * HCW];            // 8 MB, input to final GEMM
__device__ unsigned g_barc;                          // zero-init
__device__ unsigned g_barg;                          // zero-init

// ---------------- helpers ----------------
__device__ __forceinline__ float dot4(float4 a, float4 b) {
    return fmaf(a.x, b.x, fmaf(a.y, b.y, fmaf(a.z, b.z, a.w * b.w)));
}
__device__ __forceinline__ float wsum(float x) {
    x += __shfl_xor_sync(0xffffffffu, x, 16);
    x += __shfl_xor_sync(0xffffffffu, x, 8);
    x += __shfl_xor_sync(0xffffffffu, x, 4);
    x += __shfl_xor_sync(0xffffffffu, x, 2);
    x += __shfl_xor_sync(0xffffffffu, x, 1);
    return x;
}
__device__ __forceinline__ float wmax(float x) {
    x = fmaxf(x, __shfl_xor_sync(0xffffffffu, x, 16));
    x = fmaxf(x, __shfl_xor_sync(0xffffffffu, x, 8));
    x = fmaxf(x, __shfl_xor_sync(0xffffffffu, x, 4));
    x = fmaxf(x, __shfl_xor_sync(0xffffffffu, x, 2));
    x = fmaxf(x, __shfl_xor_sync(0xffffffffu, x, 1));
    return x;
}

// Grid-wide barrier (all NB blocks resident: NB <= SM count, tiny smem/regs).
__device__ __forceinline__ void grid_barrier() {
    __syncthreads();
    if (threadIdx.x == 0) {
        volatile unsigned* genp = &g_barg;
        unsigned gen = *genp;
        __threadfence();
        unsigned arrived = atomicAdd(&g_barc, 1u);
        if (arrived == NB - 1) {
            g_barc = 0;
            __threadfence();
            *genp = gen + 1;
        } else {
            while (*genp == gen) { }
            __threadfence();
        }
    }
    __syncthreads();
}

// ---------------- kernel 1: Wh = enc_out @ W_h  (B*T rows, 512 -> 256) ----------------
__global__ __launch_bounds__(256) void wh_kernel(const float* __restrict__ enc_out,
                                                 const float* __restrict__ W_h) {
    __shared__ float row[ENCD];
    const int bt = blockIdx.x;            // 4096
    const float* er = enc_out + (size_t)bt * ENCD;
    for (int i = threadIdx.x; i < ENCD; i += 256) row[i] = er[i];
    __syncthreads();
    const int a = threadIdx.x;            // 256 outputs per row
    float s0 = 0.f, s1 = 0.f, s2 = 0.f, s3 = 0.f;
    #pragma unroll 4
    for (int e = 0; e < ENCD; e += 4) {
        s0 = fmaf(row[e + 0], W_h[(e + 0) * ATTND + a], s0);
        s1 = fmaf(row[e + 1], W_h[(e + 1) * ATTND + a], s1);
        s2 = fmaf(row[e + 2], W_h[(e + 2) * ATTND + a], s2);
        s3 = fmaf(row[e + 3], W_h[(e + 3) * ATTND + a], s3);
    }
    g_Wh[(size_t)bt * ATTND + a] = (s0 + s1) + (s2 + s3);
}

// ---------------- kernel 2: persistent recurrent decoder ----------------
__global__ __launch_bounds__(NT) void decoder_kernel(
    const float* __restrict__ enc_out, const int* __restrict__ enc_mask,
    const int* __restrict__ y_in, const float* __restrict__ emb,
    const float* __restrict__ W_s, const float* __restrict__ v,
    const float* __restrict__ Wih, const float* __restrict__ Whh,
    const float* __restrict__ bih, const float* __restrict__ bhh,
    float* __restrict__ out_alpha)
{
    __shared__ float salpha[Tlen];
    __shared__ float sred[16];

    const int gtid  = blockIdx.x * NT + threadIdx.x;
    const int gwarp = gtid >> 5;
    const int lane  = threadIdx.x & 31;
    const int wid   = threadIdx.x >> 5;

    // init h = 0
    for (int i = gtid; i < Bsz * DECD; i += NTH) g_h[i] = 0.f;
    grid_barrier();

    for (int u = 0; u < Ulen; u++) {
        // ---- Phase A: Ws = h @ W_s ; gh = h @ Whh^T + bhh ----
        for (int idx = gtid; idx < Bsz * ATTND; idx += NTH) {
            const int b = idx >> 8, a = idx & 255;
            const float* hb = g_h + b * DECD;
            float s0 = 0.f, s1 = 0.f, s2 = 0.f, s3 = 0.f;
            #pragma unroll 4
            for (int d = 0; d < DECD; d += 4) {
                s0 = fmaf(hb[d + 0], W_s[(d + 0) * ATTND + a], s0);
                s1 = fmaf(hb[d + 1], W_s[(d + 1) * ATTND + a], s1);
                s2 = fmaf(hb[d + 2], W_s[(d + 2) * ATTND + a], s2);
                s3 = fmaf(hb[d + 3], W_s[(d + 3) * ATTND + a], s3);
            }
            g_Ws[idx] = (s0 + s1) + (s2 + s3);
        }
        for (int o = gwarp; o < Bsz * G3; o += NWARPS) {
            const int b = o / G3, g = o - b * G3;
            const float4* hb4 = (const float4*)(g_h + b * DECD);
            const float4* wr  = (const float4*)(Whh + (size_t)g * DECD);
            float acc = 0.f;
            #pragma unroll
            for (int j = 0; j < 4; j++) {
                const int i4 = j * 32 + lane;
                acc += dot4(hb4[i4], wr[i4]);
            }
            acc = wsum(acc);
            if (lane == 0) g_gh[o] = acc + bhh[g];
        }
        grid_barrier();

        // ---- Phase B: e[b,t] = v . tanh(Wh + Ws), mask ----
        for (int o = gwarp; o < Bsz * Tlen; o += NWARPS) {
            const int b = o >> 7;
            const float4* whp = (const float4*)(g_Wh + (size_t)o * ATTND);
            const float4* wsp = (const float4*)(g_Ws + b * ATTND);
            const float4* vp  = (const float4*)v;
            float acc = 0.f;
            #pragma unroll
            for (int j = 0; j < 2; j++) {
                const int i4 = j * 32 + lane;
                float4 w4 = whp[i4], s4 = wsp[i4], v4 = vp[i4];
                acc += v4.x * tanhf(w4.x + s4.x);
                acc += v4.y * tanhf(w4.y + s4.y);
                acc += v4.z * tanhf(w4.z + s4.z);
                acc += v4.w * tanhf(w4.w + s4.w);
            }
            acc = wsum(acc);
            if (lane == 0) g_e[o] = enc_mask[o] ? acc : -INFINITY;
        }
        grid_barrier();

        // ---- Phase C: softmax over t, alpha out, c = alpha @ enc_out, store c into hc ----
        if (blockIdx.x < Bsz) {
            const int b = blockIdx.x;
            const int tid = threadIdx.x;
            float ev = (tid < Tlen) ? g_e[b * Tlen + tid] : -INFINITY;
            float m = wmax(ev);
            if (lane == 0) sred[wid] = m;
            __syncthreads();
            if (tid == 0) {
                float mm = sred[0];
                #pragma unroll
                for (int w = 1; w < 8; w++) mm = fmaxf(mm, sred[w]);
                sred[8] = mm;
            }
            __syncthreads();
            const float mx = sred[8];
            float p = (tid < Tlen) ? expf(ev - mx) : 0.f;
            float s = wsum(p);
            if (lane == 0) sred[wid] = s;
            __syncthreads();
            if (tid == 0) {
                float ss = 0.f;
                #pragma unroll
                for (int w = 0; w < 8; w++) ss += sred[w];
                sred[9] = ss;
            }
            __syncthreads();
            const float denom = sred[9];
            if (tid < Tlen) {
                const float al = p / denom;
                salpha[tid] = al;
                out_alpha[((size_t)b * Ulen + u) * Tlen + tid] = al;
            }
            __syncthreads();
            for (int col = tid; col < ENCD; col += NT) {
                const float* ep = enc_out + (size_t)b * Tlen * ENCD + col;
                float a0 = 0.f, a1 = 0.f, a2 = 0.f, a3 = 0.f;
                #pragma unroll 4
                for (int t = 0; t < Tlen; t += 4) {
                    a0 = fmaf(salpha[t + 0], ep[(t + 0) * ENCD], a0);
                    a1 = fmaf(salpha[t + 1], ep[(t + 1) * ENCD], a1);
                    a2 = fmaf(salpha[t + 2], ep[(t + 2) * ENCD], a2);
                    a3 = fmaf(salpha[t + 3], ep[(t + 3) * ENCD], a3);
                }
                const float cc = (a0 + a1) + (a2 + a3);
                g_c[b * ENCD + col] = cc;
                g_hc[((size_t)b * Ulen + u) * HCW + DECD + col] = cc;
            }
        }
        grid_barrier();

        // ---- Phase D: gi = [emb_t, c] @ Wih^T + bih; gates; h_new; store hc ----
        for (int o = gwarp; o < Bsz * DECD; o += NWARPS) {
            const int b = o >> 9, d = o & 511;
            const int y = y_in[b * Ulen + u];
            const float4* xe = (const float4*)(emb + (size_t)y * EMBD);   // 64 x float4
            const float4* xc = (const float4*)(g_c + b * ENCD);           // 128 x float4
            const float4* w0 = (const float4*)(Wih + (size_t)d * GIN);
            const float4* w1 = (const float4*)(Wih + (size_t)(DECD + d) * GIN);
            const float4* w2 = (const float4*)(Wih + (size_t)(2 * DECD + d) * GIN);
            float ar = 0.f, az = 0.f, an = 0.f;
            #pragma unroll
            for (int j = 0; j < 6; j++) {
                const int i4 = j * 32 + lane;
                float4 xv = (i4 < 64) ? xe[i4] : xc[i4 - 64];
                ar += dot4(xv, w0[i4]);
                az += dot4(xv, w1[i4]);
                an += dot4(xv, w2[i4]);
            }
            ar = wsum(ar); az = wsum(az); an = wsum(an);
            if (lane == 0) {
                const float ir  = ar + bih[d];
                const float iz  = az + bih[DECD + d];
                const float in_ = an + bih[2 * DECD + d];
                const float hr  = g_gh[b * G3 + d];
                const float hz  = g_gh[b * G3 + DECD + d];
                const float hn  = g_gh[b * G3 + 2 * DECD + d];
                const float r = 1.f / (1.f + expf(-(ir + hr)));
                const float z = 1.f / (1.f + expf(-(iz + hz)));
                const float n = tanhf(in_ + r * hn);
                const float hp = g_h[o];
                const float hnew = (1.f - z) * n + z * hp;
                g_h[o] = hnew;
                g_hc[((size_t)b * Ulen + u) * HCW + d] = hnew;
            }
        }
        grid_barrier();
    }
}

// ---------------- kernel 3: logits = hc @ out_W^T + out_b  (2048 x 32000, K=1024) ----------------
__global__ __launch_bounds__(256) void logits_gemm(const float* __restrict__ Wt,
                                                   const float* __restrict__ bias,
                                                   float* __restrict__ C)
{
    __shared__ float As[8][128];
    __shared__ float Bs[8][128];
    const int bm = blockIdx.y * 128;
    const int bn = blockIdx.x * 128;
    const int tid = threadIdx.x;
    const int lr = tid >> 1;
    const int lk = (tid & 1) << 2;
    const int tx = tid & 15;
    const int ty = tid >> 4;

    float acc[8][8];
    #pragma unroll
    for (int i = 0; i < 8; i++)
        #pragma unroll
        for (int j = 0; j < 8; j++) acc[i][j] = 0.f;

    const float* Aptr = g_hc + (size_t)(bm + lr) * HCW + lk;
    const float* Bptr = Wt + (size_t)(bn + lr) * HCW + lk;

    for (int k0 = 0; k0 < HCW; k0 += 8) {
        const float4 a4 = *(const float4*)(Aptr + k0);
        const float4 b4 = *(const float4*)(Bptr + k0);
        As[lk + 0][lr] = a4.x; As[lk + 1][lr] = a4.y;
        As[lk + 2][lr] = a4.z; As[lk + 3][lr] = a4.w;
        Bs[lk + 0][lr] = b4.x; Bs[lk + 1][lr] = b4.y;
        Bs[lk + 2][lr] = b4.z; Bs[lk + 3][lr] = b4.w;
        __syncthreads();
        #pragma unroll
        for (int k = 0; k < 8; k++) {
            float ar[8], br[8];
            *(float4*)&ar[0] = *(const float4*)&As[k][ty * 4];
            *(float4*)&ar[4] = *(const float4*)&As[k][64 + ty * 4];
            *(float4*)&br[0] = *(const float4*)&Bs[k][tx * 4];
            *(float4*)&br[4] = *(const float4*)&Bs[k][64 + tx * 4];
            #pragma unroll
            for (int i = 0; i < 8; i++)
                #pragma unroll
                for (int j = 0; j < 8; j++)
                    acc[i][j] = fmaf(ar[i], br[j], acc[i][j]);
        }
        __syncthreads();
    }

    float bj[8];
    #pragma unroll
    for (int j = 0; j < 4; j++) {
        bj[j]     = bias[bn + tx * 4 + j];
        bj[4 + j] = bias[bn + 64 + tx * 4 + j];
    }
    #pragma unroll
    for (int i = 0; i < 8; i++) {
        const int row = bm + ty * 4 + ((i < 4) ? i : (64 + i - 4));
        float* crow = C + (size_t)row * VOCAB + bn;
        float4 o0, o1;
        o0.x = acc[i][0] + bj[0]; o0.y = acc[i][1] + bj[1];
        o0.z = acc[i][2] + bj[2]; o0.w = acc[i][3] + bj[3];
        o1.x = acc[i][4] + bj[4]; o1.y = acc[i][5] + bj[5];
        o1.z = acc[i][6] + bj[6]; o1.w = acc[i][7] + bj[7];
        *(float4*)(crow + tx * 4)      = o0;
        *(float4*)(crow + 64 + tx * 4) = o1;
    }
}

// ---------------- launch ----------------
extern "C" void kernel_launch(void* const* d_in, const int* in_sizes, int n_in,
                              void* d_out, int out_size) {
    const float* enc_out = (const float*)d_in[0];
    const int*   enc_mask= (const int*)  d_in[1];
    const int*   y_in    = (const int*)  d_in[2];
    const float* emb     = (const float*)d_in[3];
    const float* W_h     = (const float*)d_in[4];
    const float* W_s     = (const float*)d_in[5];
    const float* v       = (const float*)d_in[6];
    const float* Wih     = (const float*)d_in[7];
    const float* Whh     = (const float*)d_in[8];
    const float* bih     = (const float*)d_in[9];
    const float* bhh     = (const float*)d_in[10];
    const float* out_W   = (const float*)d_in[11];
    const float* out_b   = (const float*)d_in[12];

    float* out        = (float*)d_out;
    float* out_logits = out;
    float* out_alpha  = out + (size_t)Bsz * Ulen * VOCAB;

    wh_kernel<<<Bsz * Tlen, 256>>>(enc_out, W_h);
    decoder_kernel<<<NB, NT>>>(enc_out, enc_mask, y_in, emb, W_s, v,
                               Wih, Whh, bih, bhh, out_alpha);
    dim3 gg(VOCAB / 128, (Bsz * Ulen) / 128);
    logits_gemm<<<gg, 256>>>(out_W, out_b, out_logits);
}